// round 8
// baseline (speedup 1.0000x reference)
#include <cuda_runtime.h>
#include <cstdint>

#define N0C 1000000
#define N1C 400000
#define N2C 100000
#define PS  52          // padded fp32 row stride (multiple of 4)

typedef unsigned long long ull;

// Scratch device globals (.bss zero-init; padding cols written as exact 0)
__device__ float g_y1[(size_t)N0C * PS + 16];
__device__ float g_agg1[(size_t)N1C * PS + 16];
__device__ float g_cnt1[N1C];
__device__ float g_h[(size_t)N1C * PS + 16];
__device__ float g_y2[(size_t)N1C * PS + 16];
__device__ float g_agg2[(size_t)N2C * PS + 16];
__device__ float g_cnt2[N2C];
__device__ float g_t[(size_t)N2C * PS + 16];

// ---------------------------------------------------------------------------
__global__ void zero_all() {
    size_t stride = (size_t)gridDim.x * blockDim.x;
    size_t t0 = (size_t)blockIdx.x * blockDim.x + threadIdx.x;
    float4 z = make_float4(0.f, 0.f, 0.f, 0.f);
    for (size_t i = t0; i < (size_t)N1C * PS / 4; i += stride) ((float4*)g_agg1)[i] = z;
    for (size_t i = t0; i < (size_t)N2C * PS / 4; i += stride) ((float4*)g_agg2)[i] = z;
    for (size_t i = t0; i < N1C / 4; i += stride) ((float4*)g_cnt1)[i] = z;
    for (size_t i = t0; i < N2C / 4; i += stride) ((float4*)g_cnt2)[i] = z;
}

// ---------------------------------------------------------------------------
// Packed fp32 helpers (sm_103a f32x2 pipe; element-wise identical to fmaf)
// ---------------------------------------------------------------------------
__device__ __forceinline__ void ffma2(ull& d, ull a, ull b) {
    asm("fma.rn.f32x2 %0, %1, %2, %0;" : "+l"(d) : "l"(a), "l"(b));
}
__device__ __forceinline__ ull bcast2(float x) {
    ull r;
    asm("mov.b64 %0, {%1, %1};" : "=l"(r) : "r"(__float_as_uint(x)));
    return r;
}
__device__ __forceinline__ uint32_t smem_u32(const void* p) {
    uint32_t a;
    asm("{ .reg .u64 t; cvta.to.shared.u64 t, %1; cvt.u32.u64 %0, t; }" : "=r"(a) : "l"(p));
    return a;
}
union F4U { float4 f; ull u[2]; };
union F2U { float2 f; ull u; };

// FMA micro-block: acc[2][13] += a{0,1} * W-row(26 cols)
__device__ __forceinline__ void fma_block(ull acc[2][13], float a0f, float a1f,
                                          const float* wk)
{
    ull av0 = bcast2(a0f);
    ull av1 = bcast2(a1f);
    F4U w0, w1, w2; F2U w3;
    w0.f = *(const float4*)(wk);
    w1.f = *(const float4*)(wk + 4);
    w2.f = *(const float4*)(wk + 8);
    w3.f = *(const float2*)(wk + 12);
    ffma2(acc[0][0], av0, w0.u[0]); ffma2(acc[1][0], av1, w0.u[0]);
    ffma2(acc[0][1], av0, w0.u[1]); ffma2(acc[1][1], av1, w0.u[1]);
    ffma2(acc[0][2], av0, w1.u[0]); ffma2(acc[1][2], av1, w1.u[0]);
    ffma2(acc[0][3], av0, w1.u[1]); ffma2(acc[1][3], av1, w1.u[1]);
    ffma2(acc[0][4], av0, w2.u[0]); ffma2(acc[1][4], av1, w2.u[0]);
    ffma2(acc[0][5], av0, w2.u[1]); ffma2(acc[1][5], av1, w2.u[1]);
    ffma2(acc[0][6], av0, w3.u);    ffma2(acc[1][6], av1, w3.u);
    F4U y0, y1, y2;
    y0.f = *(const float4*)(wk + 14);
    y1.f = *(const float4*)(wk + 18);
    y2.f = *(const float4*)(wk + 22);
    ffma2(acc[0][7],  av0, y0.u[0]); ffma2(acc[1][7],  av1, y0.u[0]);
    ffma2(acc[0][8],  av0, y0.u[1]); ffma2(acc[1][8],  av1, y0.u[1]);
    ffma2(acc[0][9],  av0, y1.u[0]); ffma2(acc[1][9],  av1, y1.u[0]);
    ffma2(acc[0][10], av0, y1.u[1]); ffma2(acc[1][10], av1, y1.u[1]);
    ffma2(acc[0][11], av0, y2.u[0]); ffma2(acc[1][11], av1, y2.u[0]);
    ffma2(acc[0][12], av0, y2.u[1]); ffma2(acc[1][12], av1, y2.u[1]);
}

// Shared epilogue
template <bool AGG, bool RELU>
__device__ __forceinline__ void epilogue(ull acc[2][13], int rowbase, int nrows,
                                         int sub, const float* Bs,
                                         const float* agg, const float* cnt,
                                         float* out, int ostride, int aggstride)
{
#pragma unroll
    for (int r = 0; r < 2; r++) {
        int row = rowbase + 16 * r;
        if (row >= nrows) continue;
        float2 c[13];
#pragma unroll
        for (int j = 0; j < 13; j++) { F2U cv; cv.u = acc[r][j]; c[j] = cv.f; }
        if (AGG) {
            float ic = 1.f / fmaxf(cnt[row], 1.f);
            const float* ag = agg + (size_t)row * aggstride + sub * 26;
            const float* bs = Bs + sub * 28;
#pragma unroll
            for (int j = 0; j < 13; j++) {
                float2 g = *(const float2*)(ag + 2 * j);
                c[j].x += g.x * ic + bs[2 * j];
                c[j].y += g.y * ic + bs[2 * j + 1];
            }
        }
        if (RELU) {
#pragma unroll
            for (int j = 0; j < 13; j++) {
                c[j].x = fmaxf(c[j].x, 0.f);
                c[j].y = fmaxf(c[j].y, 0.f);
            }
        }
        float* op = out + (size_t)row * ostride + sub * 26;
#pragma unroll
        for (int j = 0; j < 13; j++) *(float2*)(op + 2 * j) = c[j];
    }
}

// ---------------------------------------------------------------------------
// Staged GEMM (D=128): out[nrows,52] = A[nrows,128] @ W[128,50] (+ epilogue)
// 256 threads, 256 rows/block, 3 blocks/SM (24 warps -> 6/SMSP for latency
// hiding). A staged in smem k-panels of 16 via cp.async.cg (coalesced,
// double-buffered), compute reads LDS.128, rows padded to 20 floats.
// Dyn smem floats: Ws[0..7168), Bs[7168..7224) pad 7232, As0[7232..12352),
// As1[12352..17472). Total 69,888 B -> 3 blocks/SM = 209,664 B.
// ---------------------------------------------------------------------------
#define WS_F  0
#define BS_F  7168
#define AS0_F 7232
#define AS1_F 12352
#define SMEM_STAGED_BYTES (17472 * 4)

template <bool AGG, bool RELU>
__global__ void __launch_bounds__(256, 3)
gemm128st(const float* __restrict__ A, const float* __restrict__ W,
          const float* __restrict__ bias, const float* __restrict__ agg,
          const float* __restrict__ cnt, float* __restrict__ out,
          int nrows, int ostride, int aggstride)
{
    extern __shared__ float sm[];
    float* Ws = sm + WS_F;
    float* Bs = sm + BS_F;
    const uint32_t smb = smem_u32(sm);

    const int tid = threadIdx.x;
    const int rowbase_blk = blockIdx.x * 256;

    // --- stage W (zero-padded 56-float rows, halves at +0/+28) ---
    for (int i = tid; i < 7168; i += 256) Ws[i] = 0.f;
    if (tid < 56) Bs[tid] = 0.f;
    __syncthreads();
    for (int i = tid; i < 128 * 50; i += 256) {
        int k = i / 50, c = i % 50;
        Ws[k * 56 + ((c < 26) ? c : c + 2)] = W[i];
    }
    if (AGG && tid < 50) Bs[(tid < 26) ? tid : tid + 2] = bias[tid];

    // --- prologue: stage A panel 0 (k 0..15) into As0 ---
#pragma unroll
    for (int j = 0; j < 4; j++) {
        int idx = j * 256 + tid;
        int row = idx >> 2, f4 = idx & 3;
        int grow = rowbase_blk + row;
        if (grow >= nrows) grow = nrows - 1;
        const float* g = A + (size_t)grow * 128 + f4 * 4;
        uint32_t s = smb + (AS0_F + row * 20 + f4 * 4) * 4;
        asm volatile("cp.async.cg.shared.global [%0], [%1], 16;" :: "r"(s), "l"(g));
    }
    asm volatile("cp.async.commit_group;");
    asm volatile("cp.async.wait_group 0;");
    __syncthreads();

    const int warp = tid >> 5, lane = tid & 31;
    const int sub = lane & 1, rid = lane >> 1;
    const int lrow0 = warp * 32 + rid;        // block-local rows
    const int rowbase = rowbase_blk + lrow0;  // global

    ull acc[2][13];
#pragma unroll
    for (int r = 0; r < 2; r++)
#pragma unroll
        for (int j = 0; j < 13; j++) acc[r][j] = 0ULL;

    int cur = 0;
#pragma unroll 1
    for (int p = 0; p < 8; p++) {
        // issue next panel
        if (p < 7) {
            uint32_t dstb = smb + ((cur ? AS0_F : AS1_F)) * 4;
#pragma unroll
            for (int j = 0; j < 4; j++) {
                int idx = j * 256 + tid;
                int row = idx >> 2, f4 = idx & 3;
                int grow = rowbase_blk + row;
                if (grow >= nrows) grow = nrows - 1;
                const float* g = A + (size_t)grow * 128 + (p + 1) * 16 + f4 * 4;
                uint32_t s = dstb + (row * 20 + f4 * 4) * 4;
                asm volatile("cp.async.cg.shared.global [%0], [%1], 16;" :: "r"(s), "l"(g));
            }
            asm volatile("cp.async.commit_group;");
        }

        const float* Asc = sm + (cur ? AS1_F : AS0_F);
        const float* a0p = Asc + lrow0 * 20;
        const float* a1p = Asc + (lrow0 + 16) * 20;
        const float* wb = Ws + (p * 16) * 56 + sub * 28;
#pragma unroll
        for (int k0 = 0; k0 < 16; k0 += 4) {
            float4 a0 = *(const float4*)(a0p + k0);
            float4 a1 = *(const float4*)(a1p + k0);
            fma_block(acc, a0.x, a1.x, wb + (k0 + 0) * 56);
            fma_block(acc, a0.y, a1.y, wb + (k0 + 1) * 56);
            fma_block(acc, a0.z, a1.z, wb + (k0 + 2) * 56);
            fma_block(acc, a0.w, a1.w, wb + (k0 + 3) * 56);
        }

        asm volatile("cp.async.wait_group 0;");
        __syncthreads();
        cur ^= 1;
    }

    epilogue<AGG, RELU>(acc, rowbase, nrows, sub, Bs, agg, cnt, out, ostride, aggstride);
}

// ---------------------------------------------------------------------------
// Small-D GEMM (D=52, direct LDG): out[nrows,52] = A[nrows,52pad] @ W
// ---------------------------------------------------------------------------
template <bool AGG, bool RELU>
__global__ void __launch_bounds__(256, 2)
gemm52(const float* __restrict__ A, const float* __restrict__ W,
       const float* __restrict__ bias, const float* __restrict__ agg,
       const float* __restrict__ cnt, float* __restrict__ out,
       int nrows, int ostride, int aggstride)
{
    __shared__ float Ws[52 * 56];
    __shared__ float Bs[56];

    const int tid = threadIdx.x;
    for (int i = tid; i < 52 * 56; i += 256) Ws[i] = 0.f;
    if (tid < 56) Bs[tid] = 0.f;
    __syncthreads();
    for (int i = tid; i < 50 * 50; i += 256) {
        int k = i / 50, c = i % 50;
        Ws[k * 56 + ((c < 26) ? c : c + 2)] = W[i];
    }
    if (AGG && tid < 50) Bs[(tid < 26) ? tid : tid + 2] = bias[tid];
    __syncthreads();

    const int warp = tid >> 5, lane = tid & 31;
    const int sub = lane & 1, rid = lane >> 1;
    const int rowbase = blockIdx.x * 256 + warp * 32 + rid;

    const float* Ar[2];
#pragma unroll
    for (int r = 0; r < 2; r++) {
        int row = rowbase + 16 * r;
        Ar[r] = A + (size_t)((row < nrows) ? row : 0) * PS;
    }

    ull acc[2][13];
#pragma unroll
    for (int r = 0; r < 2; r++)
#pragma unroll
        for (int j = 0; j < 13; j++) acc[r][j] = 0ULL;

    float4 cur0 = *(const float4*)(Ar[0]);
    float4 cur1 = *(const float4*)(Ar[1]);
#pragma unroll 1
    for (int k0 = 0; k0 < 52; k0 += 4) {
        const int kn = (k0 + 4 < 52) ? k0 + 4 : 0;
        float4 nxt0 = *(const float4*)(Ar[0] + kn);
        float4 nxt1 = *(const float4*)(Ar[1] + kn);
        const float* wb = Ws + k0 * 56 + sub * 28;
        fma_block(acc, cur0.x, cur1.x, wb);
        fma_block(acc, cur0.y, cur1.y, wb + 56);
        fma_block(acc, cur0.z, cur1.z, wb + 112);
        fma_block(acc, cur0.w, cur1.w, wb + 168);
        cur0 = nxt0; cur1 = nxt1;
    }

    epilogue<AGG, RELU>(acc, rowbase, nrows, sub, Bs, agg, cnt, out, ostride, aggstride);
}

// ---------------------------------------------------------------------------
// Scatter: agg[dst] += y[src] via red.global.add.v4.f32 (covers 52 floats
// incl. zero padding). 16 threads per edge; q==13 bumps the count.
// ---------------------------------------------------------------------------
__global__ void __launch_bounds__(256)
scatter52(const int* __restrict__ src, const int* __restrict__ dst,
          const float* __restrict__ y, float* __restrict__ agg,
          float* __restrict__ cntv, int E)
{
    int t = blockIdx.x * 256 + threadIdx.x;
    int e = t >> 4, q = t & 15;
    if (e >= E) return;
    int s = src[e], d = dst[e];
    if (q < 13) {
        float4 v = *(const float4*)(y + (size_t)s * PS + q * 4);
        float* p = agg + (size_t)d * PS + q * 4;
        asm volatile("red.global.add.v4.f32 [%0], {%1, %2, %3, %4};"
                     :: "l"(p), "f"(v.x), "f"(v.y), "f"(v.z), "f"(v.w)
                     : "memory");
    } else if (q == 13) {
        atomicAdd(cntv + d, 1.0f);
    }
}

// ---------------------------------------------------------------------------
__global__ void __launch_bounds__(256)
final_out(const float* __restrict__ t, const float* __restrict__ Wo,
          const float* __restrict__ bo, float* __restrict__ out, int n)
{
    int r = blockIdx.x * 8 + (threadIdx.x >> 5);
    if (r >= n) return;
    int l = threadIdx.x & 31;
    float p = t[(size_t)r * PS + l] * Wo[l];
    if (l < 18) p += t[(size_t)r * PS + l + 32] * Wo[l + 32];
#pragma unroll
    for (int off = 16; off; off >>= 1)
        p += __shfl_down_sync(0xffffffffu, p, off);
    if (l == 0) out[r] = fmaxf(p + bo[0], 0.f);
}

// ---------------------------------------------------------------------------
extern "C" void kernel_launch(void* const* d_in, const int* in_sizes, int n_in,
                              void* d_out, int out_size)
{
    const float* x    = (const float*)d_in[0];
    const int*   src0 = (const int*)d_in[2];
    const int*   dst0 = (const int*)d_in[3];
    const int*   src1 = (const int*)d_in[4];
    const int*   dst1 = (const int*)d_in[5];
    const float* Wl1  = (const float*)d_in[8];
    const float* bl1  = (const float*)d_in[9];
    const float* Wr1  = (const float*)d_in[10];
    const float* Wl2  = (const float*)d_in[11];
    const float* bl2  = (const float*)d_in[12];
    const float* Wr2  = (const float*)d_in[13];
    const float* Wo   = (const float*)d_in[14];
    const float* bo   = (const float*)d_in[15];
    float* out = (float*)d_out;

    const int N0 = in_sizes[0] / 128;
    const int E0 = in_sizes[2];
    const int E1 = in_sizes[4];

    float *p_y1, *p_agg1, *p_cnt1, *p_h, *p_y2, *p_agg2, *p_cnt2, *p_t;
    cudaGetSymbolAddress((void**)&p_y1,   g_y1);
    cudaGetSymbolAddress((void**)&p_agg1, g_agg1);
    cudaGetSymbolAddress((void**)&p_cnt1, g_cnt1);
    cudaGetSymbolAddress((void**)&p_h,    g_h);
    cudaGetSymbolAddress((void**)&p_y2,   g_y2);
    cudaGetSymbolAddress((void**)&p_agg2, g_agg2);
    cudaGetSymbolAddress((void**)&p_cnt2, g_cnt2);
    cudaGetSymbolAddress((void**)&p_t,    g_t);

    cudaFuncSetAttribute(gemm128st<false, false>,
                         cudaFuncAttributeMaxDynamicSharedMemorySize, SMEM_STAGED_BYTES);
    cudaFuncSetAttribute(gemm128st<true, true>,
                         cudaFuncAttributeMaxDynamicSharedMemorySize, SMEM_STAGED_BYTES);

    // 0) zero scatter accumulators
    zero_all<<<2048, 256>>>();

    // 1) y1 = x @ Wl1                                      [N0, 52]
    gemm128st<false, false><<<(N0 + 255) / 256, 256, SMEM_STAGED_BYTES>>>(
        x, Wl1, nullptr, nullptr, nullptr, p_y1, N0, PS, 0);

    // 2) agg1/cnt1 <- scatter-sum y1 over edges0
    scatter52<<<(E0 * 16 + 255) / 256, 256>>>(src0, dst0, p_y1, p_agg1, p_cnt1, E0);

    // 3) h = relu(x[:n1]@Wr1 + bl1 + agg1/cnt1)            [n1, 52]
    gemm128st<true, true><<<(N1C + 255) / 256, 256, SMEM_STAGED_BYTES>>>(
        x, Wr1, bl1, p_agg1, p_cnt1, p_h, N1C, PS, PS);

    // 4) y2 = h @ Wl2
    gemm52<false, false><<<(N1C + 255) / 256, 256>>>(
        p_h, Wl2, nullptr, nullptr, nullptr, p_y2, N1C, PS, 0);

    // 5) agg2/cnt2 <- scatter-sum y2 over edges1
    scatter52<<<(E1 * 16 + 255) / 256, 256>>>(src1, dst1, p_y2, p_agg2, p_cnt2, E1);

    // 6) t = h[:n2]@Wr2 + bl2 + agg2/cnt2                  [n2, 52]
    gemm52<true, false><<<(N2C + 255) / 256, 256>>>(
        p_h, Wr2, bl2, p_agg2, p_cnt2, p_t, N2C, PS, PS);

    // 7) out = relu(t @ Wo + bo)                           [n2, 1]
    final_out<<<(N2C + 7) / 8, 256>>>(p_t, Wo, bo, out, N2C);
}

// round 9
// speedup vs baseline: 2.2654x; 2.2654x over previous
#include <cuda_runtime.h>
#include <cstdint>

#define N0C 1000000
#define N1C 400000
#define N2C 100000
#define PS  52          // padded fp32 row stride (multiple of 4)

typedef unsigned long long ull;

// Scratch device globals (.bss zero-init; padding cols written as exact 0)
__device__ float g_y1[(size_t)N0C * PS + 16];
__device__ float g_agg1[(size_t)N1C * PS + 16];
__device__ float g_cnt1[N1C];
__device__ float g_h[(size_t)N1C * PS + 16];
__device__ float g_y2[(size_t)N1C * PS + 16];
__device__ float g_agg2[(size_t)N2C * PS + 16];
__device__ float g_cnt2[N2C];
__device__ float g_t[(size_t)N2C * PS + 16];

// ---------------------------------------------------------------------------
__global__ void zero_all() {
    size_t stride = (size_t)gridDim.x * blockDim.x;
    size_t t0 = (size_t)blockIdx.x * blockDim.x + threadIdx.x;
    float4 z = make_float4(0.f, 0.f, 0.f, 0.f);
    for (size_t i = t0; i < (size_t)N1C * PS / 4; i += stride) ((float4*)g_agg1)[i] = z;
    for (size_t i = t0; i < (size_t)N2C * PS / 4; i += stride) ((float4*)g_agg2)[i] = z;
    for (size_t i = t0; i < N1C / 4; i += stride) ((float4*)g_cnt1)[i] = z;
    for (size_t i = t0; i < N2C / 4; i += stride) ((float4*)g_cnt2)[i] = z;
}

// ---------------------------------------------------------------------------
// Packed fp32 helpers (sm_103a f32x2 pipe; element-wise identical to fmaf)
// ---------------------------------------------------------------------------
__device__ __forceinline__ void ffma2(ull& d, ull a, ull b) {
    asm("fma.rn.f32x2 %0, %1, %2, %0;" : "+l"(d) : "l"(a), "l"(b));
}
__device__ __forceinline__ ull bcast2(float x) {
    ull r;
    asm("mov.b64 %0, {%1, %1};" : "=l"(r) : "r"(__float_as_uint(x)));
    return r;
}
__device__ __forceinline__ uint32_t smem_u32(const void* p) {
    uint32_t a;
    asm("{ .reg .u64 t; cvta.to.shared.u64 t, %1; cvt.u32.u64 %0, t; }" : "=r"(a) : "l"(p));
    return a;
}
union F4U { float4 f; ull u[2]; };
union F2U { float2 f; ull u; };

// FMA micro-block shared by both GEMMs: acc[2][13] += a{0,1} * W-row(26 cols)
__device__ __forceinline__ void fma_block(ull acc[2][13], float a0f, float a1f,
                                          const float* wk)
{
    ull av0 = bcast2(a0f);
    ull av1 = bcast2(a1f);
    F4U w0, w1, w2; F2U w3;
    w0.f = *(const float4*)(wk);
    w1.f = *(const float4*)(wk + 4);
    w2.f = *(const float4*)(wk + 8);
    w3.f = *(const float2*)(wk + 12);
    ffma2(acc[0][0], av0, w0.u[0]); ffma2(acc[1][0], av1, w0.u[0]);
    ffma2(acc[0][1], av0, w0.u[1]); ffma2(acc[1][1], av1, w0.u[1]);
    ffma2(acc[0][2], av0, w1.u[0]); ffma2(acc[1][2], av1, w1.u[0]);
    ffma2(acc[0][3], av0, w1.u[1]); ffma2(acc[1][3], av1, w1.u[1]);
    ffma2(acc[0][4], av0, w2.u[0]); ffma2(acc[1][4], av1, w2.u[0]);
    ffma2(acc[0][5], av0, w2.u[1]); ffma2(acc[1][5], av1, w2.u[1]);
    ffma2(acc[0][6], av0, w3.u);    ffma2(acc[1][6], av1, w3.u);
    F4U y0, y1, y2;
    y0.f = *(const float4*)(wk + 14);
    y1.f = *(const float4*)(wk + 18);
    y2.f = *(const float4*)(wk + 22);
    ffma2(acc[0][7],  av0, y0.u[0]); ffma2(acc[1][7],  av1, y0.u[0]);
    ffma2(acc[0][8],  av0, y0.u[1]); ffma2(acc[1][8],  av1, y0.u[1]);
    ffma2(acc[0][9],  av0, y1.u[0]); ffma2(acc[1][9],  av1, y1.u[0]);
    ffma2(acc[0][10], av0, y1.u[1]); ffma2(acc[1][10], av1, y1.u[1]);
    ffma2(acc[0][11], av0, y2.u[0]); ffma2(acc[1][11], av1, y2.u[0]);
    ffma2(acc[0][12], av0, y2.u[1]); ffma2(acc[1][12], av1, y2.u[1]);
}

// Shared epilogue
template <bool AGG, bool RELU>
__device__ __forceinline__ void epilogue(ull acc[2][13], int rowbase, int nrows,
                                         int sub, const float* Bs,
                                         const float* agg, const float* cnt,
                                         float* out, int ostride, int aggstride)
{
#pragma unroll
    for (int r = 0; r < 2; r++) {
        int row = rowbase + 16 * r;
        if (row >= nrows) continue;
        float2 c[13];
#pragma unroll
        for (int j = 0; j < 13; j++) { F2U cv; cv.u = acc[r][j]; c[j] = cv.f; }
        if (AGG) {
            float ic = 1.f / fmaxf(cnt[row], 1.f);
            const float* ag = agg + (size_t)row * aggstride + sub * 26;
            const float* bs = Bs + sub * 28;
#pragma unroll
            for (int j = 0; j < 13; j++) {
                float2 g = *(const float2*)(ag + 2 * j);
                c[j].x += g.x * ic + bs[2 * j];
                c[j].y += g.y * ic + bs[2 * j + 1];
            }
        }
        if (RELU) {
#pragma unroll
            for (int j = 0; j < 13; j++) {
                c[j].x = fmaxf(c[j].x, 0.f);
                c[j].y = fmaxf(c[j].y, 0.f);
            }
        }
        float* op = out + (size_t)row * ostride + sub * 26;
#pragma unroll
        for (int j = 0; j < 13; j++) *(float2*)(op + 2 * j) = c[j];
    }
}

// ---------------------------------------------------------------------------
// Staged GEMM (D=128): out[nrows,52] = A[nrows,128] @ W[128,50] (+ epilogue)
// 256 threads, 256 rows/block, 2 blocks/SM. A staged in smem k-panels of 32
// via cp.async.cg (coalesced; double-buffered), compute reads LDS.128.
// Dyn smem floats: Ws[0..7168), Bs[7168..7224) pad to 7232, As0[7232..16448),
// As1[16448..25664). Total 102,656 B.
// ---------------------------------------------------------------------------
#define WS_F  0
#define BS_F  7168
#define AS0_F 7232
#define AS1_F 16448
#define SMEM_STAGED_BYTES (25664 * 4)

template <bool AGG, bool RELU>
__global__ void __launch_bounds__(256, 2)
gemm128st(const float* __restrict__ A, const float* __restrict__ W,
          const float* __restrict__ bias, const float* __restrict__ agg,
          const float* __restrict__ cnt, float* __restrict__ out,
          int nrows, int ostride, int aggstride)
{
    extern __shared__ float sm[];
    float* Ws = sm + WS_F;
    float* Bs = sm + BS_F;
    const uint32_t smb = smem_u32(sm);

    const int tid = threadIdx.x;
    const int rowbase_blk = blockIdx.x * 256;

    // --- stage W (zero-padded 56-float rows, halves at +0/+28) ---
    for (int i = tid; i < 7168; i += 256) Ws[i] = 0.f;
    if (tid < 56) Bs[tid] = 0.f;
    __syncthreads();
    for (int i = tid; i < 128 * 50; i += 256) {
        int k = i / 50, c = i % 50;
        Ws[k * 56 + ((c < 26) ? c : c + 2)] = W[i];
    }
    if (AGG && tid < 50) Bs[(tid < 26) ? tid : tid + 2] = bias[tid];

    // --- prologue: stage A panel 0 into As0 ---
    {
#pragma unroll
        for (int j = 0; j < 8; j++) {
            int idx = j * 256 + tid;
            int row = idx >> 3, f4 = idx & 7;
            int grow = rowbase_blk + row;
            if (grow >= nrows) grow = nrows - 1;
            const float* g = A + (size_t)grow * 128 + f4 * 4;
            uint32_t s = smb + (AS0_F + row * 36 + f4 * 4) * 4;
            asm volatile("cp.async.cg.shared.global [%0], [%1], 16;"
                         :: "r"(s), "l"(g));
        }
        asm volatile("cp.async.commit_group;");
    }
    asm volatile("cp.async.wait_group 0;");
    __syncthreads();

    const int warp = tid >> 5, lane = tid & 31;
    const int sub = lane & 1, rid = lane >> 1;
    const int lrow0 = warp * 32 + rid;        // block-local rows
    const int rowbase = rowbase_blk + lrow0;  // global

    ull acc[2][13];
#pragma unroll
    for (int r = 0; r < 2; r++)
#pragma unroll
        for (int j = 0; j < 13; j++) acc[r][j] = 0ULL;

    int cur = 0;
#pragma unroll 1
    for (int p = 0; p < 4; p++) {
        // issue next panel
        if (p < 3) {
            uint32_t dstb = smb + ((cur ? AS0_F : AS1_F)) * 4;
#pragma unroll
            for (int j = 0; j < 8; j++) {
                int idx = j * 256 + tid;
                int row = idx >> 3, f4 = idx & 7;
                int grow = rowbase_blk + row;
                if (grow >= nrows) grow = nrows - 1;
                const float* g = A + (size_t)grow * 128 + (p + 1) * 32 + f4 * 4;
                uint32_t s = dstb + (row * 36 + f4 * 4) * 4;
                asm volatile("cp.async.cg.shared.global [%0], [%1], 16;"
                             :: "r"(s), "l"(g));
            }
            asm volatile("cp.async.commit_group;");
        }

        const float* Asc = sm + (cur ? AS1_F : AS0_F);
        const float* a0p = Asc + lrow0 * 36;
        const float* a1p = Asc + (lrow0 + 16) * 36;
        const float* wb = Ws + (p * 32) * 56 + sub * 28;
#pragma unroll
        for (int k0 = 0; k0 < 32; k0 += 4) {
            float4 a0 = *(const float4*)(a0p + k0);
            float4 a1 = *(const float4*)(a1p + k0);
            fma_block(acc, a0.x, a1.x, wb + (k0 + 0) * 56);
            fma_block(acc, a0.y, a1.y, wb + (k0 + 1) * 56);
            fma_block(acc, a0.z, a1.z, wb + (k0 + 2) * 56);
            fma_block(acc, a0.w, a1.w, wb + (k0 + 3) * 56);
        }

        asm volatile("cp.async.wait_group 0;");
        __syncthreads();
        cur ^= 1;
    }

    epilogue<AGG, RELU>(acc, rowbase, nrows, sub, Bs, agg, cnt, out, ostride, aggstride);
}

// ---------------------------------------------------------------------------
// Small-D GEMM (D=52, direct LDG): out[nrows,52] = A[nrows,52pad] @ W
// ---------------------------------------------------------------------------
template <bool AGG, bool RELU>
__global__ void __launch_bounds__(256, 2)
gemm52(const float* __restrict__ A, const float* __restrict__ W,
       const float* __restrict__ bias, const float* __restrict__ agg,
       const float* __restrict__ cnt, float* __restrict__ out,
       int nrows, int ostride, int aggstride)
{
    __shared__ float Ws[52 * 56];
    __shared__ float Bs[56];

    const int tid = threadIdx.x;
    for (int i = tid; i < 52 * 56; i += 256) Ws[i] = 0.f;
    if (tid < 56) Bs[tid] = 0.f;
    __syncthreads();
    for (int i = tid; i < 50 * 50; i += 256) {
        int k = i / 50, c = i % 50;
        Ws[k * 56 + ((c < 26) ? c : c + 2)] = W[i];
    }
    if (AGG && tid < 50) Bs[(tid < 26) ? tid : tid + 2] = bias[tid];
    __syncthreads();

    const int warp = tid >> 5, lane = tid & 31;
    const int sub = lane & 1, rid = lane >> 1;
    const int rowbase = blockIdx.x * 256 + warp * 32 + rid;

    const float* Ar[2];
#pragma unroll
    for (int r = 0; r < 2; r++) {
        int row = rowbase + 16 * r;
        Ar[r] = A + (size_t)((row < nrows) ? row : 0) * PS;
    }

    ull acc[2][13];
#pragma unroll
    for (int r = 0; r < 2; r++)
#pragma unroll
        for (int j = 0; j < 13; j++) acc[r][j] = 0ULL;

    float4 cur0 = *(const float4*)(Ar[0]);
    float4 cur1 = *(const float4*)(Ar[1]);
#pragma unroll 1
    for (int k0 = 0; k0 < 52; k0 += 4) {
        const int kn = (k0 + 4 < 52) ? k0 + 4 : 0;
        float4 nxt0 = *(const float4*)(Ar[0] + kn);
        float4 nxt1 = *(const float4*)(Ar[1] + kn);
        const float* wb = Ws + k0 * 56 + sub * 28;
        fma_block(acc, cur0.x, cur1.x, wb);
        fma_block(acc, cur0.y, cur1.y, wb + 56);
        fma_block(acc, cur0.z, cur1.z, wb + 112);
        fma_block(acc, cur0.w, cur1.w, wb + 168);
        cur0 = nxt0; cur1 = nxt1;
    }

    epilogue<AGG, RELU>(acc, rowbase, nrows, sub, Bs, agg, cnt, out, ostride, aggstride);
}

// ---------------------------------------------------------------------------
// Scatter: agg[dst] += y[src] via red.global.add.v4.f32 (covers 52 floats
// incl. zero padding). One warp = 2 edges: lanes 0-12 edge A, 13-25 edge B,
// lane 26 cntA, lane 27 cntB.
// ---------------------------------------------------------------------------
__global__ void __launch_bounds__(256)
scatter52(const int* __restrict__ src, const int* __restrict__ dst,
          const float* __restrict__ y, float* __restrict__ agg,
          float* __restrict__ cntv, int E)
{
    int warpid = blockIdx.x * 8 + (threadIdx.x >> 5);
    int lane = threadIdx.x & 31;
    int e0 = warpid * 2;
    if (e0 >= E) return;

    if (lane < 26) {
        int half = (lane >= 13);
        int e = e0 + half;
        if (e < E) {
            int q = lane - half * 13;
            int s = src[e], d = dst[e];
            float4 v = *(const float4*)(y + (size_t)s * PS + q * 4);
            float* p = agg + (size_t)d * PS + q * 4;
            asm volatile("red.global.add.v4.f32 [%0], {%1, %2, %3, %4};"
                         :: "l"(p), "f"(v.x), "f"(v.y), "f"(v.z), "f"(v.w)
                         : "memory");
        }
    } else if (lane < 28) {
        int e = e0 + (lane - 26);
        if (e < E) atomicAdd(cntv + dst[e], 1.0f);
    }
}

// ---------------------------------------------------------------------------
__global__ void __launch_bounds__(256)
final_out(const float* __restrict__ t, const float* __restrict__ Wo,
          const float* __restrict__ bo, float* __restrict__ out, int n)
{
    int r = blockIdx.x * 8 + (threadIdx.x >> 5);
    if (r >= n) return;
    int l = threadIdx.x & 31;
    float p = t[(size_t)r * PS + l] * Wo[l];
    if (l < 18) p += t[(size_t)r * PS + l + 32] * Wo[l + 32];
#pragma unroll
    for (int off = 16; off; off >>= 1)
        p += __shfl_down_sync(0xffffffffu, p, off);
    if (l == 0) out[r] = fmaxf(p + bo[0], 0.f);
}

// ---------------------------------------------------------------------------
extern "C" void kernel_launch(void* const* d_in, const int* in_sizes, int n_in,
                              void* d_out, int out_size)
{
    const float* x    = (const float*)d_in[0];
    const int*   src0 = (const int*)d_in[2];
    const int*   dst0 = (const int*)d_in[3];
    const int*   src1 = (const int*)d_in[4];
    const int*   dst1 = (const int*)d_in[5];
    const float* Wl1  = (const float*)d_in[8];
    const float* bl1  = (const float*)d_in[9];
    const float* Wr1  = (const float*)d_in[10];
    const float* Wl2  = (const float*)d_in[11];
    const float* bl2  = (const float*)d_in[12];
    const float* Wr2  = (const float*)d_in[13];
    const float* Wo   = (const float*)d_in[14];
    const float* bo   = (const float*)d_in[15];
    float* out = (float*)d_out;

    const int N0 = in_sizes[0] / 128;
    const int E0 = in_sizes[2];
    const int E1 = in_sizes[4];

    float *p_y1, *p_agg1, *p_cnt1, *p_h, *p_y2, *p_agg2, *p_cnt2, *p_t;
    cudaGetSymbolAddress((void**)&p_y1,   g_y1);
    cudaGetSymbolAddress((void**)&p_agg1, g_agg1);
    cudaGetSymbolAddress((void**)&p_cnt1, g_cnt1);
    cudaGetSymbolAddress((void**)&p_h,    g_h);
    cudaGetSymbolAddress((void**)&p_y2,   g_y2);
    cudaGetSymbolAddress((void**)&p_agg2, g_agg2);
    cudaGetSymbolAddress((void**)&p_cnt2, g_cnt2);
    cudaGetSymbolAddress((void**)&p_t,    g_t);

    cudaFuncSetAttribute(gemm128st<false, false>,
                         cudaFuncAttributeMaxDynamicSharedMemorySize, SMEM_STAGED_BYTES);
    cudaFuncSetAttribute(gemm128st<true, true>,
                         cudaFuncAttributeMaxDynamicSharedMemorySize, SMEM_STAGED_BYTES);

    // 0) zero scatter accumulators
    zero_all<<<2048, 256>>>();

    // 1) y1 = x @ Wl1                                      [N0, 52]
    gemm128st<false, false><<<(N0 + 255) / 256, 256, SMEM_STAGED_BYTES>>>(
        x, Wl1, nullptr, nullptr, nullptr, p_y1, N0, PS, 0);

    // 2) agg1/cnt1 <- scatter-sum y1 over edges0  (2 edges per warp)
    scatter52<<<(E0 / 2 + 7) / 8, 256>>>(src0, dst0, p_y1, p_agg1, p_cnt1, E0);

    // 3) h = relu(x[:n1]@Wr1 + bl1 + agg1/cnt1)            [n1, 52]
    gemm128st<true, true><<<(N1C + 255) / 256, 256, SMEM_STAGED_BYTES>>>(
        x, Wr1, bl1, p_agg1, p_cnt1, p_h, N1C, PS, PS);

    // 4) y2 = h @ Wl2
    gemm52<false, false><<<(N1C + 255) / 256, 256>>>(
        p_h, Wl2, nullptr, nullptr, nullptr, p_y2, N1C, PS, 0);

    // 5) agg2/cnt2 <- scatter-sum y2 over edges1
    scatter52<<<(E1 / 2 + 7) / 8, 256>>>(src1, dst1, p_y2, p_agg2, p_cnt2, E1);

    // 6) t = h[:n2]@Wr2 + bl2 + agg2/cnt2                  [n2, 52]
    gemm52<true, false><<<(N2C + 255) / 256, 256>>>(
        p_h, Wr2, bl2, p_agg2, p_cnt2, p_t, N2C, PS, PS);

    // 7) out = relu(t @ Wo + bo)                           [n2, 1]
    final_out<<<(N2C + 7) / 8, 256>>>(p_t, Wo, bo, out, N2C);
}